// round 1
// baseline (speedup 1.0000x reference)
#include <cuda_runtime.h>
#include <math.h>

// Scalar scratch accumulator (allocation-free per harness rules).
__device__ double g_acc;

static constexpr int B_DIM = 8192;
static constexpr int N_PTS = 1024;
static constexpr int THREADS = 128;

__device__ __forceinline__ void euler_to_matrix(float a, float b, float c, float* R) {
    float ca, sa, cb, sb, cc, sc;
    __sincosf(a, &sa, &ca);   // fast math ok? use precise to match ref better
    // Use precise sin/cos for accuracy against float32 JAX reference:
    sa = sinf(a); ca = cosf(a);
    sb = sinf(b); cb = cosf(b);
    sc = sinf(c); cc = cosf(c);
    // R = Rx(a) * Ry(b) * Rz(c)
    // M = Ry*Rz = [[cb*cc, -cb*sc, sb],[sc, cc, 0],[-sb*cc, sb*sc, cb]]
    R[0] = cb * cc;
    R[1] = -cb * sc;
    R[2] = sb;
    R[3] = ca * sc + sa * sb * cc;
    R[4] = ca * cc - sa * sb * sc;
    R[5] = -sa * cb;
    R[6] = sa * sc - ca * sb * cc;
    R[7] = sa * cc + ca * sb * sc;
    R[8] = ca * cb;
}

__global__ void zero_acc_kernel() { g_acc = 0.0; }

__global__ __launch_bounds__(THREADS)
void add_loss_kernel(const float* __restrict__ pred,
                     const float* __restrict__ mode,
                     const float* __restrict__ gt,
                     const float* __restrict__ point) {
    __shared__ float Dsh[9];
    __shared__ float warp_sums[THREADS / 32];

    const int b = blockIdx.x;

    if (threadIdx.x == 0) {
        // manifold2euler
        const float m1 = pred[b * 4 + 0];
        const float m2 = pred[b * 4 + 1];
        const float m3 = pred[b * 4 + 2];
        const float m4 = pred[b * 4 + 3];
        const float sgn = (mode[b] > 0.5f) ? 1.0f : -1.0f;
        const float denom = m1 * m1 + m2 * m2 + m3 * m3;
        const float e2 = sgn * asinf(sqrtf(m3 * m3 / denom));
        const float se2 = sinf(e2);
        const float ce2 = cosf(e2);
        const float e3 = atan2f(m4, m3 / (se2 + 1e-9f));
        const float tmp = ce2 * cosf(e3);
        const float e1 = atan2f(m2 / tmp, m1 / tmp);
        // (euler3 wrap by +2pi in ref only changes the angle by a full period:
        //  sin/cos used in the rotation matrix are unaffected -> skip it.)

        float Rp[9], Rg[9];
        euler_to_matrix(e1, e2, e3, Rp);
        euler_to_matrix(gt[b * 3 + 0], gt[b * 3 + 1], gt[b * 3 + 2], Rg);
        #pragma unroll
        for (int i = 0; i < 9; i++) Dsh[i] = Rp[i] - Rg[i];
    }
    __syncthreads();

    // Load D into registers (rows indexed j, cols k; out_k = sum_j p_j * D[j][k])
    const float d00 = Dsh[0], d01 = Dsh[1], d02 = Dsh[2];
    const float d10 = Dsh[3], d11 = Dsh[4], d12 = Dsh[5];
    const float d20 = Dsh[6], d21 = Dsh[7], d22 = Dsh[8];

    const float* __restrict__ pp = point + (size_t)b * N_PTS * 3;

    float sum = 0.0f;
    #pragma unroll
    for (int it = 0; it < N_PTS / THREADS; it++) {
        const int i = it * THREADS + threadIdx.x;
        const float p0 = pp[i * 3 + 0];
        const float p1 = pp[i * 3 + 1];
        const float p2 = pp[i * 3 + 2];
        const float q0 = fmaf(p0, d00, fmaf(p1, d10, p2 * d20));
        const float q1 = fmaf(p0, d01, fmaf(p1, d11, p2 * d21));
        const float q2 = fmaf(p0, d02, fmaf(p1, d12, p2 * d22));
        sum += sqrtf(fmaf(q0, q0, fmaf(q1, q1, q2 * q2)));
    }

    // warp reduce
    #pragma unroll
    for (int off = 16; off > 0; off >>= 1)
        sum += __shfl_xor_sync(0xffffffffu, sum, off);
    if ((threadIdx.x & 31) == 0) warp_sums[threadIdx.x >> 5] = sum;
    __syncthreads();
    if (threadIdx.x == 0) {
        float s = 0.0f;
        #pragma unroll
        for (int w = 0; w < THREADS / 32; w++) s += warp_sums[w];
        atomicAdd(&g_acc, (double)s);
    }
}

__global__ void finalize_kernel(float* __restrict__ out) {
    out[0] = (float)(g_acc / ((double)B_DIM * (double)N_PTS));
}

extern "C" void kernel_launch(void* const* d_in, const int* in_sizes, int n_in,
                              void* d_out, int out_size) {
    const float* pred  = (const float*)d_in[0];   // (8192, 4)
    const float* mode  = (const float*)d_in[1];   // (8192,)
    const float* gt    = (const float*)d_in[2];   // (8192, 3)
    const float* point = (const float*)d_in[3];   // (8192, 1024, 3)
    float* out = (float*)d_out;

    zero_acc_kernel<<<1, 1>>>();
    add_loss_kernel<<<B_DIM, THREADS>>>(pred, mode, gt, point);
    finalize_kernel<<<1, 1>>>(out);
}

// round 3
// speedup vs baseline: 1.1262x; 1.1262x over previous
#include <cuda_runtime.h>
#include <math.h>

static constexpr int B_DIM = 8192;
static constexpr int N_PTS = 1024;
static constexpr int THREADS = 256;          // main kernel block size
static constexpr int PTS_PER_THREAD = N_PTS / THREADS;  // 4

// Allocation-free scratch (__device__ globals per harness rules).
__device__ double g_acc;
__device__ unsigned int g_ticket;
__device__ float g_D[B_DIM * 9];             // D = R_pred - R_gt per batch row

__device__ __forceinline__ void euler_to_matrix(float a, float b, float c, float* R) {
    const float sa = sinf(a), ca = cosf(a);
    const float sb = sinf(b), cb = cosf(b);
    const float sc = sinf(c), cc = cosf(c);
    // R = Rx(a) * Ry(b) * Rz(c)
    R[0] = cb * cc;
    R[1] = -cb * sc;
    R[2] = sb;
    R[3] = ca * sc + sa * sb * cc;
    R[4] = ca * cc - sa * sb * sc;
    R[5] = -sa * cb;
    R[6] = sa * sc - ca * sb * cc;
    R[7] = sa * cc + ca * sb * sc;
    R[8] = ca * cb;
}

// Kernel 1: per-row trig + matrix difference, fully parallel (8192 threads).
// Also resets the cross-replay accumulator state (stream-ordered before kernel 2).
__global__ __launch_bounds__(256)
void precompute_kernel(const float* __restrict__ pred,
                       const float* __restrict__ mode,
                       const float* __restrict__ gt) {
    const int b = blockIdx.x * blockDim.x + threadIdx.x;
    if (b == 0) { g_acc = 0.0; g_ticket = 0u; }
    if (b >= B_DIM) return;

    const float m1 = pred[b * 4 + 0];
    const float m2 = pred[b * 4 + 1];
    const float m3 = pred[b * 4 + 2];
    const float m4 = pred[b * 4 + 3];
    const float sgn = (mode[b] > 0.5f) ? 1.0f : -1.0f;
    const float denom = m1 * m1 + m2 * m2 + m3 * m3;
    const float e2 = sgn * asinf(sqrtf(m3 * m3 / denom));
    const float se2 = sinf(e2);
    const float ce2 = cosf(e2);
    const float e3 = atan2f(m4, m3 / (se2 + 1e-9f));
    const float tmp = ce2 * cosf(e3);
    const float e1 = atan2f(m2 / tmp, m1 / tmp);
    // (ref's +2pi wrap of euler3 only shifts by a full period; sin/cos unchanged)

    float Rp[9], Rg[9];
    euler_to_matrix(e1, e2, e3, Rp);
    euler_to_matrix(gt[b * 3 + 0], gt[b * 3 + 1], gt[b * 3 + 2], Rg);
    #pragma unroll
    for (int i = 0; i < 9; i++) g_D[b * 9 + i] = Rp[i] - Rg[i];
}

// Kernel 2: stream points with wavefront-minimal float4 loads, shared staging,
// per-point norm, block reduce, global double accumulate, last-block finalize.
__global__ __launch_bounds__(THREADS)
void add_loss_kernel(const float* __restrict__ point, float* __restrict__ out) {
    __shared__ float sh[N_PTS * 3];          // 12 KB point tile
    __shared__ float warp_sums[THREADS / 32];

    const int b = blockIdx.x;
    const int t = threadIdx.x;

    // Contiguous float4 loads: 768 float4s, 3 per thread, fully coalesced.
    const float4* __restrict__ p4 = (const float4*)(point + (size_t)b * (N_PTS * 3));
    float4 v0 = p4[0 * THREADS + t];
    float4 v1 = p4[1 * THREADS + t];
    float4 v2 = p4[2 * THREADS + t];

    // D matrix (uniform loads, L1/L2 broadcast — negligible).
    const float* __restrict__ D = g_D + b * 9;
    const float d00 = D[0], d01 = D[1], d02 = D[2];
    const float d10 = D[3], d11 = D[4], d12 = D[5];
    const float d20 = D[6], d21 = D[7], d22 = D[8];

    float4* sh4 = (float4*)sh;
    sh4[0 * THREADS + t] = v0;               // STS.128, conflict-free
    sh4[1 * THREADS + t] = v1;
    sh4[2 * THREADS + t] = v2;
    __syncthreads();

    // Each thread: points t, t+256, t+512, t+768.
    // LDS bank = (3t + j) mod 32; gcd(3,32)=1 -> conflict-free.
    float sum = 0.0f;
    #pragma unroll
    for (int q = 0; q < PTS_PER_THREAD; q++) {
        const int i = q * THREADS + t;
        const float p0 = sh[3 * i + 0];
        const float p1 = sh[3 * i + 1];
        const float p2 = sh[3 * i + 2];
        const float q0 = fmaf(p0, d00, fmaf(p1, d10, p2 * d20));
        const float q1 = fmaf(p0, d01, fmaf(p1, d11, p2 * d21));
        const float q2 = fmaf(p0, d02, fmaf(p1, d12, p2 * d22));
        sum += sqrtf(fmaf(q0, q0, fmaf(q1, q1, q2 * q2)));
    }

    // Warp reduce
    #pragma unroll
    for (int off = 16; off > 0; off >>= 1)
        sum += __shfl_xor_sync(0xffffffffu, sum, off);
    if ((t & 31) == 0) warp_sums[t >> 5] = sum;
    __syncthreads();

    if (t == 0) {
        float s = 0.0f;
        #pragma unroll
        for (int w = 0; w < THREADS / 32; w++) s += warp_sums[w];
        atomicAdd(&g_acc, (double)s);
        __threadfence();
        const unsigned int ticket = atomicAdd(&g_ticket, 1u);
        if (ticket == (unsigned int)(gridDim.x - 1)) {
            // Last block: all prior atomics visible. Atomic read of the total.
            const double total = atomicAdd(&g_acc, 0.0);
            out[0] = (float)(total * (1.0 / ((double)B_DIM * (double)N_PTS)));
        }
    }
}

extern "C" void kernel_launch(void* const* d_in, const int* in_sizes, int n_in,
                              void* d_out, int out_size) {
    const float* pred  = (const float*)d_in[0];   // (8192, 4)
    const float* mode  = (const float*)d_in[1];   // (8192,)
    const float* gt    = (const float*)d_in[2];   // (8192, 3)
    const float* point = (const float*)d_in[3];   // (8192, 1024, 3)
    float* out = (float*)d_out;

    precompute_kernel<<<B_DIM / 256, 256>>>(pred, mode, gt);
    add_loss_kernel<<<B_DIM, THREADS>>>(point, out);
}